// round 15
// baseline (speedup 1.0000x reference)
#include <cuda_runtime.h>
#include <cuda_fp16.h>

// HamiltonianFlow: 100 RK4 steps, 400 sequential MLP-gradient evals.
// 128 CTAs x 2 samples, NT=512 (16 warps, 4/SMSP), split-K halves c=t>>8.
// fp16 weights, fp32 accumulation (R14 numerics, rel_err ~8e-5).
//
// Thread (i, c):
//   forward:  z_i^c = sum_{f in [128c,128c+128)} q_f * W[f][i]
//             from smem hw[i][f] (fp16, stride 264 halves -> conflict-free
//             LDS.128 rows), cvt to f32 pairs -> fma.rn.f32x2.
//   backward: F_i^c = sum_{j in [128c,128c+128)} W[i][j] * u_j
//             ENTIRELY from rc[64] (__half2 register cache, 64 regs).
// Partials combined via zp/Fp smem buffers (c=1 -> c=0), 2 barriers/region.
// No LDG in loop, no shuffles, no G-section; regs ~110 < 128 cap.

#define STEPS 100
#define DTV   0.01f
#define NT    512
#define NCTA  128
#define NREG  (4 * STEPS + 1)
#define HSTRIDE 264

typedef unsigned long long ull;

#define HW_BYTES (256 * HSTRIDE * 2)              // 135168
#define SMEM_BYTES (HW_BYTES + (1024 + 1024 + 512 + 512) * 4)

__device__ __forceinline__ void fma2(ull& d, ull a, ull b) {
    asm("fma.rn.f32x2 %0, %1, %2, %0;" : "+l"(d) : "l"(a), "l"(b));
}
__device__ __forceinline__ ull pkf(float lo, float hi) {
    ull d;
    asm("mov.b64 %0, {%1, %2};" : "=l"(d) : "f"(lo), "f"(hi));
    return d;
}
__device__ __forceinline__ float psum(ull v) {
    return __uint_as_float((unsigned)(v & 0xffffffffu)) +
           __uint_as_float((unsigned)(v >> 32));
}

__global__ __launch_bounds__(NT, 1)
void hflow_kernel(const float* __restrict__ x0,
                  const float* __restrict__ W1,
                  const float* __restrict__ b1,
                  const float* __restrict__ W2,
                  float* __restrict__ out)
{
    extern __shared__ char smraw[];
    __half* hw = (__half*)smraw;                  // [256 i][HSTRIDE f] fp16
    float*  qb = (float*)(smraw + HW_BYTES);      // [2 buf][2 samp][256]
    float*  ub = qb + 1024;                       // [2 buf][2 samp][256]
    float*  zp = ub + 1024;                       // [2 samp][256] c=1 fwd partial
    float*  Fp = zp + 512;                        // [2 samp][256] c=1 bwd partial

    const int t = threadIdx.x;
    const int c = t >> 8;                         // K-half
    const int i = t & 255;                        // unit index
    const int f0 = c << 7;                        // this half's feat/j range base

    // ---- stage fp16 transposed weights: hw[j*HSTRIDE + f] = W1[f][j] ----
    for (int idx = t; idx < 65536; idx += NT) {
        int f = idx >> 8, j = idx & 255;
        hw[j * HSTRIDE + f] = __float2half_rn(W1[idx]);
    }

    // ---- backward register cache: W1[i][f0 .. f0+128) as 64 half2 ----
    __half2 rc[64];
    {
        const float4* wr = (const float4*)(W1 + i * 256 + f0);
#pragma unroll
        for (int m = 0; m < 32; m++) {
            float4 v = __ldg(wr + m);
            rc[2 * m]     = __float22half2_rn(make_float2(v.x, v.y));
            rc[2 * m + 1] = __float22half2_rn(make_float2(v.z, v.w));
        }
    }

    const float rb1 = b1[i];
    const float rw2 = W2[i];

    const int s0 = blockIdx.x * 2;
    float2 st0 = ((const float2*)x0)[s0 * 256 + i];
    float2 st1 = ((const float2*)x0)[(s0 + 1) * 256 + i];
    float q0[2], p0[2], Aq[2], Ap[2], pc[2];
    q0[0] = st0.x; p0[0] = st0.y;
    q0[1] = st1.x; p0[1] = st1.y;
    Ap[0] = Ap[1] = 0.f;

    if (c == 0) {                                 // stage-0 q into buf 0
        qb[i]       = q0[0];
        qb[256 + i] = q0[1];
    }
    __syncthreads();

    const __half* wrow = hw + i * HSTRIDE;
    const float h2 = 0.5f * DTV;
    const float d6 = DTV / 6.f;

    for (int r = 0; r < NREG; r++) {
        const int par = r & 1;
        const float* qc = qb + par * 512;
        float*       qn = qb + (par ^ 1) * 512;
        float*       un = ub + par * 512;
        const float* uc = ub + (par ^ 1) * 512;
        const bool has_f = (r < NREG - 1);
        const bool has_b = (r > 0);
        const int sf = r & 3;
        const float cq = (sf == 2) ? DTV : h2;    // c[sf+1]

        // ---- forward partial: z_i^c over feats [f0, f0+128) ----
        float z0 = 0.f, z1 = 0.f;
        if (has_f) {
            ull zA0 = 0, zA1 = 0, zB0 = 0, zB1 = 0;
#pragma unroll 8
            for (int k = 0; k < 128; k += 8) {
                const int f = f0 + k;
                uint4 wv = *(const uint4*)(wrow + f);
                ulonglong2 qa0 = *(const ulonglong2*)&qc[f];
                ulonglong2 qa1 = *(const ulonglong2*)&qc[f + 4];
                ulonglong2 qx0 = *(const ulonglong2*)&qc[256 + f];
                ulonglong2 qx1 = *(const ulonglong2*)&qc[256 + f + 4];
                float2 w0 = __half22float2(*(__half2*)&wv.x);
                float2 w1 = __half22float2(*(__half2*)&wv.y);
                float2 w2 = __half22float2(*(__half2*)&wv.z);
                float2 w3 = __half22float2(*(__half2*)&wv.w);
                ull W0p = pkf(w0.x, w0.y), W1p = pkf(w1.x, w1.y);
                ull W2p = pkf(w2.x, w2.y), W3p = pkf(w3.x, w3.y);
                fma2(zA0, W0p, qa0.x); fma2(zA1, W1p, qa0.y);
                fma2(zA0, W2p, qa1.x); fma2(zA1, W3p, qa1.y);
                fma2(zB0, W0p, qx0.x); fma2(zB1, W1p, qx0.y);
                fma2(zB0, W2p, qx1.x); fma2(zB1, W3p, qx1.y);
            }
            z0 = psum(zA0) + psum(zA1);
            z1 = psum(zB0) + psum(zB1);
            if (c) { zp[i] = z0; zp[256 + i] = z1; }
        }

        // ---- backward partial: F_i^c over j in [f0, f0+128), all regs ----
        float Fs0 = 0.f, Fs1 = 0.f;
        if (has_b) {
            ull fA0 = 0, fA1 = 0, fB0 = 0, fB1 = 0;
#pragma unroll
            for (int k = 0; k < 64; k += 2) {     // j = f0+2k .. f0+2k+3
                ulonglong2 u0 = *(const ulonglong2*)&uc[f0 + 2 * k];
                ulonglong2 u1 = *(const ulonglong2*)&uc[256 + f0 + 2 * k];
                float2 wA = __half22float2(rc[k]);
                float2 wB = __half22float2(rc[k + 1]);
                ull WA = pkf(wA.x, wA.y), WB = pkf(wB.x, wB.y);
                fma2(fA0, WA, u0.x); fma2(fA1, WB, u0.y);
                fma2(fB0, WA, u1.x); fma2(fB1, WB, u1.y);
            }
            Fs0 = psum(fA0) + psum(fA1);
            Fs1 = psum(fB0) + psum(fB1);
            if (c) { Fp[i] = Fs0; Fp[256 + i] = Fs1; }
        }

        __syncthreads();                          // X: zp/Fp published

        if (c == 0) {
            if (has_f) {
                float zz0 = z0 + zp[i] + rb1;
                float zz1 = z1 + zp[256 + i] + rb1;
                float e0 = __expf(2.f * zz0);
                float e1 = __expf(2.f * zz1);
                float th0 = 1.f - 2.f / (e0 + 1.f);
                float th1 = 1.f - 2.f / (e1 + 1.f);
                un[i]       = rw2 * (1.f - th0 * th0);
                un[256 + i] = rw2 * (1.f - th1 * th1);
            }
            if (has_b) {
                float F[2];
                F[0] = Fs0 + Fp[i];
                F[1] = Fs1 + Fp[256 + i];
                const int sb = (r - 1) & 3;
                if (sb == 3) {
#pragma unroll
                    for (int m = 0; m < 2; m++) {
                        Ap[m] += F[m];
                        p0[m] -= d6 * Ap[m];
                        Ap[m] = 0.f;
                        pc[m] = p0[m];
                        Aq[m] = pc[m];
                    }
                } else {
                    const float wb_ = (sb == 0) ? 1.f : 2.f;
                    const float cn  = (sb == 2) ? DTV : h2;
                    const float wn  = (sb == 2) ? 1.f : 2.f;
#pragma unroll
                    for (int m = 0; m < 2; m++) {
                        Ap[m] += wb_ * F[m];
                        pc[m] = p0[m] - cn * F[m];
                        Aq[m] += wn * pc[m];
                    }
                }
                if (has_f) {
                    if (sf == 3) {
                        q0[0] += d6 * Aq[0];
                        q0[1] += d6 * Aq[1];
                        qn[i]       = q0[0];
                        qn[256 + i] = q0[1];
                    } else {
                        qn[i]       = q0[0] + cq * pc[0];
                        qn[256 + i] = q0[1] + cq * pc[1];
                    }
                }
            } else {
                // r == 0: stage 0
                pc[0] = p0[0]; Aq[0] = pc[0];
                pc[1] = p0[1]; Aq[1] = pc[1];
                qn[i]       = q0[0] + cq * pc[0];
                qn[256 + i] = q0[1] + cq * pc[1];
            }
        }

        __syncthreads();                          // Y: un/qn ready
    }

    if (c == 0) {
        ((float2*)out)[s0 * 256 + i]       = make_float2(q0[0], p0[0]);
        ((float2*)out)[(s0 + 1) * 256 + i] = make_float2(q0[1], p0[1]);
    }
}

extern "C" void kernel_launch(void* const* d_in, const int* in_sizes, int n_in,
                              void* d_out, int out_size) {
    const float* x0 = (const float*)d_in[0];
    const float* W1 = (const float*)d_in[1];
    const float* b1 = (const float*)d_in[2];
    const float* W2 = (const float*)d_in[3];
    cudaFuncSetAttribute(hflow_kernel,
                         cudaFuncAttributeMaxDynamicSharedMemorySize, SMEM_BYTES);
    hflow_kernel<<<NCTA, NT, SMEM_BYTES>>>(x0, W1, b1, W2, (float*)d_out);
}